// round 6
// baseline (speedup 1.0000x reference)
#include <cuda_runtime.h>
#include <math.h>
#include <stdint.h>

// ln(2)^2 — final scale to convert lg2-unit squared-loss into natural-log units
#define LN2SQ 0.4804530139182014
#define LOG2E 1.4426950408889634f

typedef unsigned long long u64;

// statically-zeroed accumulators; kernel self-resets them after each use.
__device__ double g_accum = 0.0;
__device__ unsigned int g_count = 0u;

// ---- scalar MUFU intrinsics ----
__device__ __forceinline__ float f_rcp(float x)   { float y; asm("rcp.approx.f32 %0, %1;"   : "=f"(y) : "f"(x)); return y; }
__device__ __forceinline__ float f_rsqrt(float x) { float y; asm("rsqrt.approx.f32 %0, %1;" : "=f"(y) : "f"(x)); return y; }
__device__ __forceinline__ float f_sqrt(float x)  { float y; asm("sqrt.approx.f32 %0, %1;"  : "=f"(y) : "f"(x)); return y; }
__device__ __forceinline__ float f_lg2(float x)   { float y; asm("lg2.approx.f32 %0, %1;"   : "=f"(y) : "f"(x)); return y; }
__device__ __forceinline__ float f_cos(float x)   { float y; asm("cos.approx.f32 %0, %1;"   : "=f"(y) : "f"(x)); return y; }

// ---- packed f32x2 ops (sm_100+; FFMA2/FADD2/FMUL2 in SASS) ----
__device__ __forceinline__ u64 pk(float lo, float hi) { u64 r; asm("mov.b64 %0, {%1, %2};" : "=l"(r) : "f"(lo), "f"(hi)); return r; }
__device__ __forceinline__ void upk(u64 v, float& lo, float& hi) { asm("mov.b64 {%0, %1}, %2;" : "=f"(lo), "=f"(hi) : "l"(v)); }
__device__ __forceinline__ u64 add2(u64 a, u64 b) { u64 d; asm("add.rn.f32x2 %0, %1, %2;" : "=l"(d) : "l"(a), "l"(b)); return d; }
__device__ __forceinline__ u64 mul2(u64 a, u64 b) { u64 d; asm("mul.rn.f32x2 %0, %1, %2;" : "=l"(d) : "l"(a), "l"(b)); return d; }
__device__ __forceinline__ u64 fma2(u64 a, u64 b, u64 c) { u64 d; asm("fma.rn.f32x2 %0, %1, %2, %3;" : "=l"(d) : "l"(a), "l"(b), "l"(c)); return d; }
__device__ __forceinline__ u64 bc2(float c) { return pk(c, c); }                 // broadcast
__device__ __forceinline__ u64 sub2(u64 a, u64 b, u64 neg1) { return fma2(b, neg1, a); }  // a - b

// scalar tail of the per-eigenvalue path: given w0>=w1>=w2 (one matrix),
// return alpha,beta,gamma of logm(A) = a*I + b*A + c*A^2 in lg2 units,
// with the R5-proven degenerate-pair guards.
__device__ __forceinline__ void divdiff(float w0, float w1, float w2,
                                        float& alp, float& bet, float& gam) {
    float f0 = f_lg2(w0);
    float f1 = f_lg2(w1);
    float f2 = f_lg2(w2);
    float e01 = w0 - w1, e12 = w1 - w2, e02 = w0 - w2;
    float d01 = (e01 > 0.01f * (w0 + w1)) ? (f0 - f1) * f_rcp(e01)
                                          : 2.0f * LOG2E * f_rcp(w0 + w1);
    float d12 = (e12 > 0.01f * (w1 + w2)) ? (f1 - f2) * f_rcp(e12)
                                          : 2.0f * LOG2E * f_rcp(w1 + w2);
    if (e02 > 0.005f * (w0 + w2)) {
        gam = (d01 - d12) * f_rcp(e02);
    } else {
        float q = (w0 + w1 + w2) * (1.0f / 3.0f);
        float iq = f_rcp(q);
        gam = -0.5f * LOG2E * iq * iq;       // f''(q)/2 for f = lg2
    }
    bet = d01 - gam * (w0 + w1);
    alp = f0 - d01 * w0 + gam * w0 * w1;
}

__global__ void __launch_bounds__(256)
loss_kernel(const float* __restrict__ d1, const float* __restrict__ d2,
            int nmat, float* __restrict__ out, double inv_n, unsigned int nblocks) {
    int i = blockIdx.x * blockDim.x + threadIdx.x;
    float s = 0.0f;
    if (i < nmat) {
        const float* g1 = d1 + (size_t)i * 9;
        const float* g2 = d2 + (size_t)i * 9;

        const u64 NEG1 = bc2(-1.0f);

        // pack: lo half = D1 matrix, hi half = D2 matrix (entrywise |.|)
        u64 a00 = pk(fabsf(g1[0]), fabsf(g2[0]));
        u64 a10 = pk(fabsf(g1[3]), fabsf(g2[3]));
        u64 a11 = pk(fabsf(g1[4]), fabsf(g2[4]));
        u64 a20 = pk(fabsf(g1[6]), fabsf(g2[6]));
        u64 a21 = pk(fabsf(g1[7]), fabsf(g2[7]));
        u64 a22 = pk(fabsf(g1[8]), fabsf(g2[8]));

        // ---- eigen setup (trigonometric method), packed ----
        u64 q  = mul2(add2(add2(a00, a11), a22), bc2(1.0f / 3.0f));
        u64 b00 = sub2(a00, q, NEG1);
        u64 b11 = sub2(a11, q, NEG1);
        u64 b22 = sub2(a22, q, NEG1);
        u64 sq10 = mul2(a10, a10);
        u64 sq20 = mul2(a20, a20);
        u64 sq21 = mul2(a21, a21);
        u64 p1 = add2(add2(sq10, sq20), sq21);
        u64 p2 = fma2(b00, b00, add2(p1, p1));
        p2 = fma2(b11, b11, p2);
        p2 = fma2(b22, b22, p2);
        u64 x2 = mul2(p2, bc2(1.0f / 6.0f));

        float xl, xh;
        upk(x2, xl, xh);
        float rsl = f_rsqrt(fmaxf(xl, 1e-30f));
        float rsh = f_rsqrt(fmaxf(xh, 1e-30f));
        u64 rs = pk(rsl, rsh);
        u64 p  = mul2(x2, rs);               // sqrt(x)

        u64 t1 = sub2(mul2(b11, b22), sq21, NEG1);
        u64 t2 = sub2(mul2(a10, b22), mul2(a21, a20), NEG1);
        u64 t3 = sub2(mul2(a10, a21), mul2(b11, a20), NEG1);
        u64 detB = mul2(b00, t1);
        detB = sub2(detB, mul2(a10, t2), NEG1);
        detB = fma2(a20, t3, detB);

        u64 r2 = mul2(mul2(detB, bc2(0.5f)), mul2(mul2(rs, rs), rs));
        float rl, rh;
        upk(r2, rl, rh);
        rl = fmaxf(-1.0f, fminf(1.0f, rl));  // also squashes NaN -> 1
        rh = fmaxf(-1.0f, fminf(1.0f, rh));

        // ---- acos poly (A&S 4.4.46), packed on |r| ----
        u64 av = pk(fabsf(rl), fabsf(rh));
        u64 pp = bc2(-0.0012624911f);
        pp = fma2(pp, av, bc2( 0.0066700901f));
        pp = fma2(pp, av, bc2(-0.0170881256f));
        pp = fma2(pp, av, bc2( 0.0308918810f));
        pp = fma2(pp, av, bc2(-0.0501743046f));
        pp = fma2(pp, av, bc2( 0.0889789874f));
        pp = fma2(pp, av, bc2(-0.2145988016f));
        pp = fma2(pp, av, bc2( 1.5707963050f));
        float pl, ph;
        upk(pp, pl, ph);

        float ql, qh; upk(q, ql, qh);
        float ppl, pph; upk(p, ppl, pph);

        float tl = f_sqrt(fmaxf(1.0f - fabsf(rl), 0.0f)) * pl;
        float th = f_sqrt(fmaxf(1.0f - fabsf(rh), 0.0f)) * ph;
        float acl = (rl < 0.0f) ? (3.14159265359f - tl) : tl;
        float ach = (rh < 0.0f) ? (3.14159265359f - th) : th;

        // lo half eigenvalues
        float phil = acl * (1.0f / 3.0f);
        float tpl  = 2.0f * ppl;
        float w0l = fmaf(tpl, f_cos(phil), ql);
        float w2l = fmaf(tpl, f_cos(phil + 2.0943951023931953f), ql);
        float w1l = 3.0f * ql - w0l - w2l;
        // hi half eigenvalues
        float phih = ach * (1.0f / 3.0f);
        float tph  = 2.0f * pph;
        float w0h = fmaf(tph, f_cos(phih), qh);
        float w2h = fmaf(tph, f_cos(phih + 2.0943951023931953f), qh);
        float w1h = 3.0f * qh - w0h - w2h;

        float al, bl, gl, ah, bh, gh;
        divdiff(w0l, w1l, w2l, al, bl, gl);
        divdiff(w0h, w1h, w2h, ah, bh, gh);
        u64 alp = pk(al, ah);
        u64 bet = pk(bl, bh);
        u64 gam = pk(gl, gh);

        // ---- A^2 (6 unique entries), packed ----
        u64 s00 = fma2(a00, a00, add2(sq10, sq20));
        u64 s11 = fma2(a11, a11, add2(sq10, sq21));
        u64 s22 = fma2(a22, a22, add2(sq20, sq21));
        u64 s10 = fma2(a10, add2(a00, a11), mul2(a20, a21));
        u64 s20 = fma2(a20, add2(a00, a22), mul2(a10, a21));
        u64 s21 = fma2(a21, add2(a11, a22), mul2(a10, a20));

        // ---- L = alp*I + bet*A + gam*A^2, packed ----
        u64 L00 = fma2(gam, s00, fma2(bet, a00, alp));
        u64 L11 = fma2(gam, s11, fma2(bet, a11, alp));
        u64 L22 = fma2(gam, s22, fma2(bet, a22, alp));
        u64 L10 = fma2(gam, s10, mul2(bet, a10));
        u64 L20 = fma2(gam, s20, mul2(bet, a20));
        u64 L21 = fma2(gam, s21, mul2(bet, a21));

        // ---- cross-half difference and squared accumulation ----
        float u, v, t;
        upk(L00, u, v); t = u - v; s = fmaf(t, t, s);
        upk(L11, u, v); t = u - v; s = fmaf(t, t, s);
        upk(L22, u, v); t = u - v; s = fmaf(t, t, s);
        upk(L10, u, v); t = u - v; s = fmaf(2.0f * t, t, s);  // off-diagonals twice
        upk(L20, u, v); t = u - v; s = fmaf(2.0f * t, t, s);
        upk(L21, u, v); t = u - v; s = fmaf(2.0f * t, t, s);
    }

    // ---- block reduction ----
    #pragma unroll
    for (int off = 16; off > 0; off >>= 1)
        s += __shfl_xor_sync(0xffffffffu, s, off);

    __shared__ float sh[8];
    int lane = threadIdx.x & 31;
    int warp = threadIdx.x >> 5;
    if (lane == 0) sh[warp] = s;
    __syncthreads();
    if (warp == 0) {
        float v = (lane < 8) ? sh[lane] : 0.0f;
        #pragma unroll
        for (int off = 4; off > 0; off >>= 1)
            v += __shfl_xor_sync(0xffu, v, off);
        if (lane == 0) {
            atomicAdd(&g_accum, (double)v);
            __threadfence();
            unsigned int ticket = atomicInc(&g_count, nblocks - 1u);
            if (ticket == nblocks - 1u) {
                out[0] = (float)(g_accum * inv_n);
                g_accum = 0.0;    // restore invariant for next call/replay
            }
        }
    }
}

extern "C" void kernel_launch(void* const* d_in, const int* in_sizes, int n_in,
                              void* d_out, int out_size) {
    const float* d1 = (const float*)d_in[0];
    const float* d2 = (const float*)d_in[1];
    int n_elems = in_sizes[0];          // nmat * 9
    int nmat = n_elems / 9;

    int threads = 256;
    unsigned int blocks = (unsigned int)((nmat + threads - 1) / threads);
    // inv_n includes the ln(2)^2 rescale (logs were computed in base 2)
    double inv_n = LN2SQ / (double)n_elems;
    loss_kernel<<<blocks, threads>>>(d1, d2, nmat, (float*)d_out, inv_n, blocks);
}